// round 9
// baseline (speedup 1.0000x reference)
#include <cuda_runtime.h>
#include <cuda_fp16.h>
#include <math.h>
#include <stdint.h>

// Problem constants
#define BB    16
#define CC    64
#define HWSZ  4096
#define NPIX  65536
#define KK    1024
#define DD    64
#define NEL   4194304
#define GATHER_BLOCKS 4096     // NEL / 4 / 256

// Device scratch
__device__ __align__(16) int    g_idx[NPIX];
__device__ float                g_counts[KK];
__device__ float                g_cnorm[KK];
__device__ float                g_part[GATHER_BLOCKS];
__device__ __align__(16) __half g_ch[KK * DD];   // [-c] fp16: [8 chunks][64 d][64 pairs][2]
__device__ int                  g_cnmax_i;       // bits of max cn (monotonic, deterministic)

// Pure-PTX f16x2 ops on scalar u32 registers (no address-taking, no arrays)
#define HFMA2(acc, a, b) \
    asm("fma.rn.f16x2 %0, %1, %2, %0;" : "+r"(acc) : "r"(a), "r"(b))
#define HMIN2(d, a, b) \
    asm("min.f16x2 %0, %1, %2;" : "=r"(d) : "r"(a), "r"(b))

__device__ __forceinline__ float h2lo(uint32_t u) {
    return __half2float(__ushort_as_half((unsigned short)(u & 0xffffu)));
}
__device__ __forceinline__ float h2hi(uint32_t u) {
    return __half2float(__ushort_as_half((unsigned short)(u >> 16)));
}

// ---------------------------------------------------------------------------
// Kernel 1: prep — exact cn, negated fp16 pair-interleaved codebook, stats
// ---------------------------------------------------------------------------
__global__ void prep_kernel(const float* __restrict__ cb) {
    int k = blockIdx.x * 256 + threadIdx.x;
    if (k >= KK) return;
    const int ch   = k >> 7;
    const int pair = (k & 127) >> 1;
    const int lane = k & 1;
    float s = 0.f;
    #pragma unroll
    for (int d = 0; d < DD; d++) {
        float v = cb[k * DD + d];
        s = __fadd_rn(s, __fmul_rn(v, v));   // reference-exact cn
        g_ch[(((ch * 64 + d) * 64) + pair) * 2 + lane] = __float2half(-v);
    }
    g_cnorm[k]  = s;
    g_counts[k] = 0.f;
    atomicMax(&g_cnmax_i, __float_as_int(s));   // positive floats: int order ok
}

// ---------------------------------------------------------------------------
// Exact reference-rounding score, single code copy (__noinline__).
// xs/cns live in shared memory (generic pointers; refine is rare).
// ---------------------------------------------------------------------------
__device__ __noinline__ unsigned long long exact_key(
    const float* xs, const float* cns, const float* __restrict__ cb,
    int px, int n, float ns) {
    const float4* cr = (const float4*)(cb + (size_t)n * DD);
    float a = 0.f;
    #pragma unroll
    for (int w = 0; w < 16; w++) {
        float4 c = __ldg(&cr[w]);
        a = __fmaf_rn(xs[(w * 4 + 0) * 128 + px], c.x, a);
        a = __fmaf_rn(xs[(w * 4 + 1) * 128 + px], c.y, a);
        a = __fmaf_rn(xs[(w * 4 + 2) * 128 + px], c.z, a);
        a = __fmaf_rn(xs[(w * 4 + 3) * 128 + px], c.w, a);
    }
    float sE = __fsub_rn(__fadd_rn(ns, cns[n]), __fmul_rn(2.f, a));
    return ((unsigned long long)__float_as_uint(sE) << 32) | (unsigned)n;
}

// ---------------------------------------------------------------------------
// Kernel 2: HFMA2 (PTX) coarse keys + margin filter + noinline exact refine
// 256 threads, 128 pixels/block; thread (tx,ty): px tx*8..+7, codes ty*8..+7
// smem: xs f32[64][128] | xd u32[64][128] | cs u32[64][64] | cns[1024] | nss[128]
// ---------------------------------------------------------------------------
extern __shared__ char smraw[];

__global__ void __launch_bounds__(256, 2)
coarse_kernel(const float* __restrict__ in, const float* __restrict__ cb) {
    float*    xs  = (float*)smraw;                  // 32768 B
    uint32_t* xd  = (uint32_t*)(smraw + 32768);     // 32768 B (dup'd fp16x2 x)
    uint32_t* cs  = (uint32_t*)(smraw + 65536);     // 16384 B (paired -c fp16x2)
    float*    cns = (float*)(smraw + 81920);        // 4096 B
    float*    nss = (float*)(smraw + 86016);        // 512 B  (total 86528)

    const int tid = threadIdx.x;
    const int tx  = tid & 15;
    const int ty  = tid >> 4;

    const int n0  = blockIdx.x * 128;
    const int b   = n0 >> 12;
    const int hw0 = n0 & 4095;
    const float* xin = in + (size_t)b * CC * HWSZ + hw0;

    for (int i = tid; i < 8192; i += 256) {
        int d = i >> 7, p = i & 127;
        float v = xin[(size_t)d * HWSZ + p];
        xs[d * 128 + p] = v;
        __half h = __float2half(v);
        uint32_t us = (uint32_t)__half_as_ushort(h);
        xd[d * 128 + p] = us | (us << 16);
    }
    for (int i = tid; i < KK; i += 256) cns[i] = g_cnorm[i];
    __syncthreads();

    if (tid < 128) {   // exact ||x||^2 (reference rounding)
        float s = 0.f;
        #pragma unroll
        for (int d = 0; d < DD; d++) {
            float v = xs[d * 128 + tid];
            s = __fadd_rn(s, __fmul_rn(v, v));
        }
        nss[tid] = s;
    }
    __syncthreads();

    const float cnmax = __int_as_float(g_cnmax_i);

    float m[8], Mg[8];
    unsigned long long best[8];
    #pragma unroll
    for (int i = 0; i < 8; i++) {
        float ns = nss[tx * 8 + i];
        m[i]    = 3.4e38f;
        Mg[i]   = 0.08f * sqrtf(ns * cnmax) + cnmax + 1e-4f;
        best[i] = ~0ull;
    }

    for (int ch = 0; ch < 8; ch++) {
        __syncthreads();
        {
            const uint4* src = (const uint4*)((const char*)g_ch + ch * 16384);
            uint4* dst = (uint4*)cs;
            #pragma unroll
            for (int i = 0; i < 4; i++) dst[tid + i * 256] = src[tid + i * 256];
        }
        __syncthreads();

        uint32_t acc[8][4];
        #pragma unroll
        for (int i = 0; i < 8; i++)
            #pragma unroll
            for (int j = 0; j < 4; j++) acc[i][j] = 0u;

        // coarse keys: acc[i][j] += x_i * (-c_pair_j), fp16x2 via PTX
        #pragma unroll 4
        for (int d = 0; d < 64; d++) {
            uint4 xa = *(const uint4*)(xd + d * 128 + tx * 8);
            uint4 xb = *(const uint4*)(xd + d * 128 + tx * 8 + 4);
            uint4 cv = *(const uint4*)(cs + d * 64 + ty * 4);
            uint32_t xv[8], cw[4];
            xv[0] = xa.x; xv[1] = xa.y; xv[2] = xa.z; xv[3] = xa.w;
            xv[4] = xb.x; xv[5] = xb.y; xv[6] = xb.z; xv[7] = xb.w;
            cw[0] = cv.x; cw[1] = cv.y; cw[2] = cv.z; cw[3] = cv.w;
            #pragma unroll
            for (int i = 0; i < 8; i++)
                #pragma unroll
                for (int j = 0; j < 4; j++)
                    HFMA2(acc[i][j], xv[i], cw[j]);
        }

        // epilogue: fold, update running min, rare refine via noinline call
        #pragma unroll
        for (int i = 0; i < 8; i++) {
            uint32_t r01, r23, r;
            HMIN2(r01, acc[i][0], acc[i][1]);
            HMIN2(r23, acc[i][2], acc[i][3]);
            HMIN2(r, r01, r23);
            float mn = fminf(h2lo(r), h2hi(r));
            if (mn < m[i]) m[i] = mn;
            float thr = m[i] + Mg[i];
            if (mn < thr) {
                const int px = tx * 8 + i;
                const float ns = nss[px];
                #pragma unroll
                for (int j = 0; j < 4; j++) {
                    uint32_t a = acc[i][j];
                    float k0 = h2lo(a);
                    float k1 = h2hi(a);
                    if (k0 < thr) {
                        unsigned long long key = exact_key(
                            xs, cns, cb, px, ch * 128 + ty * 8 + j * 2, ns);
                        if (key < best[i]) best[i] = key;
                    }
                    if (k1 < thr) {
                        unsigned long long key = exact_key(
                            xs, cns, cb, px, ch * 128 + ty * 8 + j * 2 + 1, ns);
                        if (key < best[i]) best[i] = key;
                    }
                }
            }
        }
    }

    // cross-thread (over ty) u64 min reduction per pixel; reuse smem
    __syncthreads();
    unsigned long long* rb = (unsigned long long*)smraw;   // [16][128] = 16KB
    #pragma unroll
    for (int i = 0; i < 8; i++) rb[ty * 128 + tx * 8 + i] = best[i];
    __syncthreads();
    if (tid < 128) {
        unsigned long long bk = rb[tid];
        #pragma unroll
        for (int t = 1; t < 16; t++) {
            unsigned long long v = rb[t * 128 + tid];
            if (v < bk) bk = v;
        }
        int bidx = (int)(bk & 0xffffffffull);
        g_idx[n0 + tid] = bidx;
        atomicAdd(&g_counts[bidx], 1.0f);   // integer-valued: deterministic
    }
}

// ---------------------------------------------------------------------------
// Kernel 3: gather quantized output + per-block loss partial.
// Loads vectorized; outq = out+1 (4 mod 16) so stores stay scalar.
// ---------------------------------------------------------------------------
__global__ void gather_loss_kernel(const float* __restrict__ in,
                                   const float* __restrict__ cb,
                                   float* __restrict__ outq) {
    const int tid = threadIdx.x;
    const int e   = (blockIdx.x * 256 + tid) * 4;

    int b  = e >> 18;
    int r  = e & 262143;
    int c  = r >> 12;
    int hw = r & 4095;           // multiple of 4
    const int4 gi = *(const int4*)&g_idx[(b << 12) | hw];

    float4 x = *(const float4*)(in + e);
    float q0 = __ldg(&cb[gi.x * DD + c]);
    float q1 = __ldg(&cb[gi.y * DD + c]);
    float q2 = __ldg(&cb[gi.z * DD + c]);
    float q3 = __ldg(&cb[gi.w * DD + c]);

    float d0 = q0 - x.x, d1 = q1 - x.y, d2 = q2 - x.z, d3 = q3 - x.w;
    outq[e + 0] = x.x + d0;
    outq[e + 1] = x.y + d1;
    outq[e + 2] = x.z + d2;
    outq[e + 3] = x.w + d3;
    float part = d0 * d0 + d1 * d1 + d2 * d2 + d3 * d3;

    #pragma unroll
    for (int o2 = 16; o2; o2 >>= 1)
        part += __shfl_xor_sync(0xffffffffu, part, o2);
    __shared__ float ws[8];
    if ((tid & 31) == 0) ws[tid >> 5] = part;
    __syncthreads();
    if (tid == 0) {
        float s = 0.f;
        #pragma unroll
        for (int w = 0; w < 8; w++) s += ws[w];
        g_part[blockIdx.x] = s;
    }
}

// ---------------------------------------------------------------------------
// Kernel 4: finalize loss + perplexity
// ---------------------------------------------------------------------------
__global__ void finalize_kernel(const float* __restrict__ beta,
                                float* __restrict__ loss_out,
                                float* __restrict__ pp_out) {
    const int t = threadIdx.x;   // 1024

    float ls = 0.f;
    #pragma unroll
    for (int i = 0; i < GATHER_BLOCKS / 1024; i++)
        ls += g_part[t * (GATHER_BLOCKS / 1024) + i];

    float em  = g_counts[t] * (1.0f / (float)NPIX);
    float ent = em * logf(em + 1e-10f);

    #pragma unroll
    for (int o = 16; o; o >>= 1) {
        ls  += __shfl_xor_sync(0xffffffffu, ls, o);
        ent += __shfl_xor_sync(0xffffffffu, ent, o);
    }
    __shared__ float wl[32], we[32];
    if ((t & 31) == 0) { wl[t >> 5] = ls; we[t >> 5] = ent; }
    __syncthreads();
    if (t == 0) {
        float tl = 0.f, te = 0.f;
        #pragma unroll
        for (int w = 0; w < 32; w++) { tl += wl[w]; te += we[w]; }
        float mean = tl / (float)NEL;
        *loss_out = (1.0f + *beta) * 10.0f * mean;   // KLD_SCALE = 10
        *pp_out   = expf(-te);
    }
}

// ---------------------------------------------------------------------------
// Launch
// ---------------------------------------------------------------------------
extern "C" void kernel_launch(void* const* d_in, const int* in_sizes, int n_in,
                              void* d_out, int out_size) {
    const float* in   = nullptr;
    const float* cb   = nullptr;
    const float* beta = nullptr;
    for (int i = 0; i < n_in; i++) {
        if      (in_sizes[i] == NEL)     in   = (const float*)d_in[i];
        else if (in_sizes[i] == KK * DD) cb   = (const float*)d_in[i];
        else if (in_sizes[i] == 1)       beta = (const float*)d_in[i];
    }

    float* out      = (float*)d_out;
    float* loss_out = out;
    float* q_out    = out + 1;
    float* pp_out   = out + (out_size - 1);

    const int smem_bytes = 86528;
    cudaFuncSetAttribute(coarse_kernel,
                         cudaFuncAttributeMaxDynamicSharedMemorySize, smem_bytes);

    prep_kernel<<<(KK + 255) / 256, 256>>>(cb);
    coarse_kernel<<<NPIX / 128, 256, smem_bytes>>>(in, cb);
    gather_loss_kernel<<<GATHER_BLOCKS, 256>>>(in, cb, q_out);
    finalize_kernel<<<1, 1024>>>(beta, loss_out, pp_out);
}

// round 10
// speedup vs baseline: 5.8551x; 5.8551x over previous
#include <cuda_runtime.h>
#include <math.h>
#include <stdint.h>

// Problem constants
#define BB    16
#define CC    64
#define HWSZ  4096
#define NPIX  65536
#define KK    1024
#define DD    64
#define NEL   4194304
#define TILE_P 128
#define CHUNK  128
#define GATHER_BLOCKS 4096     // NEL / 4 / 256

// Device scratch
__device__ __align__(16) int    g_idx[NPIX];
__device__ float                g_counts[KK];
__device__ float                g_cnorm[KK];
__device__ float                g_part[GATHER_BLOCKS];
__device__ __align__(16) float2 g_cdup[KK * DD];  // [(chunk)(d)(k)] = (c,c)

// Packed f32x2 helpers. FMA2 halves are two independent correctly-rounded
// fp32 FMAs (validated bit-exact vs reference in R6).
#define UNPACK2(lo, hi, src) \
    asm("mov.b64 {%0, %1}, %2;" : "=f"(lo), "=f"(hi) : "l"(src))
#define FMA2(acc, a, b) \
    asm("fma.rn.f32x2 %0, %1, %2, %0;" : "+l"(acc) : "l"(a), "l"(b))
#define LDS_V2U64(a, b, addr) \
    asm volatile("ld.shared.v2.u64 {%0, %1}, [%2];" \
                 : "=l"(a), "=l"(b) : "r"(addr))

// ---------------------------------------------------------------------------
// Kernel 1: codebook norms + duplicated-pair codebook image + zero histogram
// ---------------------------------------------------------------------------
__global__ void prep_kernel(const float* __restrict__ cb) {
    int k = blockIdx.x * blockDim.x + threadIdx.x;
    if (k >= KK) return;
    const int ch = k >> 7;        // chunk of 128 codes
    const int k0 = k & 127;
    float s = 0.f;
    #pragma unroll
    for (int d = 0; d < DD; d++) {
        float v = cb[k * DD + d];
        s = __fadd_rn(s, __fmul_rn(v, v));            // reference-exact cn
        g_cdup[(ch * 64 + d) * 128 + k0] = make_float2(v, v);
    }
    g_cnorm[k]  = s;
    g_counts[k] = 0.f;
}

// ---------------------------------------------------------------------------
// Kernel 2: exact argmin via packed-fp32 FFMA2 GEMM (zero packing in loop)
// 256 thr, 128 px x 128-code chunks; thread (tx,ty): px tx*8..+7 (4 pairs),
// codes ty*8..+7. smem: xs f32[64][128] | csd f32x2[64][128] | cns | nss
// ---------------------------------------------------------------------------
extern __shared__ char smraw[];

__global__ void __launch_bounds__(256, 2)
argmin_kernel(const float* __restrict__ in, const float* __restrict__ cb) {
    float* xs  = (float*)smraw;                    // 32768 B
    char*  csd = smraw + 32768;                    // 65536 B (dup'd code pairs)
    float* cns = (float*)(smraw + 98304);          // 512 B
    float* nss = (float*)(smraw + 98816);          // 512 B  (total 99328)

    const int tid = threadIdx.x;
    const int tx  = tid & 15;
    const int ty  = tid >> 4;

    const int n0  = blockIdx.x * TILE_P;
    const int b   = n0 >> 12;
    const int hw0 = n0 & 4095;
    const float* xin = in + (size_t)b * CC * HWSZ + hw0;

    // load x tile: xs[d][p]  (coalesced); adjacent pixels form f32x2 pairs
    for (int i = tid; i < 64 * 128; i += 256) {
        int d = i >> 7, p = i & 127;
        xs[d * 128 + p] = xin[(size_t)d * HWSZ + p];
    }
    __syncthreads();

    // exact ||x||^2 (reference rounding)
    if (tid < 128) {
        float s = 0.f;
        #pragma unroll
        for (int d = 0; d < DD; d++) {
            float v = xs[d * 128 + tid];
            s = __fadd_rn(s, __fmul_rn(v, v));
        }
        nss[tid] = s;
    }

    float bd[8];
    int   bi[8];
    #pragma unroll
    for (int i = 0; i < 8; i++) { bd[i] = 3.4e38f; bi[i] = 0; }

    const uint32_t xs_b = (uint32_t)__cvta_generic_to_shared(xs);
    const uint32_t cs_b = (uint32_t)__cvta_generic_to_shared(csd);

    unsigned long long acc2[4][8];

    for (int kc = 0; kc < KK; kc += CHUNK) {
        __syncthreads();
        // copy duplicated code chunk: 64KB = 4096 uint4
        {
            const uint4* src = (const uint4*)(g_cdup + (kc >> 7) * 8192);
            uint4* dst = (uint4*)csd;
            #pragma unroll
            for (int i = 0; i < 16; i++) dst[tid + i * 256] = src[tid + i * 256];
        }
        if (tid < CHUNK) cns[tid] = g_cnorm[kc + tid];
        __syncthreads();

        #pragma unroll
        for (int i = 0; i < 4; i++)
            #pragma unroll
            for (int j = 0; j < 8; j++) acc2[i][j] = 0ull;

        uint32_t xaddr = xs_b + tx * 32;   // + d*512
        uint32_t caddr = cs_b + ty * 64;   // + d*1024

        // packed dot: each u64 lane = independent sequential-d fp32 FMA chain
        #pragma unroll 2
        for (int d = 0; d < 64; d++) {
            unsigned long long xp[4], cd[8];
            LDS_V2U64(xp[0], xp[1], xaddr);
            LDS_V2U64(xp[2], xp[3], xaddr + 16);
            LDS_V2U64(cd[0], cd[1], caddr);
            LDS_V2U64(cd[2], cd[3], caddr + 16);
            LDS_V2U64(cd[4], cd[5], caddr + 32);
            LDS_V2U64(cd[6], cd[7], caddr + 48);
            #pragma unroll
            for (int i = 0; i < 4; i++)
                #pragma unroll
                for (int j = 0; j < 8; j++)
                    FMA2(acc2[i][j], xp[i], cd[j]);
            xaddr += 512;
            caddr += 1024;
        }

        // min update: score fl(fl(ns+cn) - fl(2*dot)); 2*dot exact in fp32 so
        // fmaf(-2, dot, fl(ns+cn)) is bit-identical. ascending k + '<' keeps
        // first-index min within thread.
        #pragma unroll
        for (int i2 = 0; i2 < 4; i2++) {
            float ns0 = nss[tx * 8 + i2 * 2];
            float ns1 = nss[tx * 8 + i2 * 2 + 1];
            #pragma unroll
            for (int j = 0; j < 8; j++) {
                float lo, hi;
                UNPACK2(lo, hi, acc2[i2][j]);
                float cn = cns[ty * 8 + j];
                float s0 = __fmaf_rn(-2.0f, lo, __fadd_rn(ns0, cn));
                float s1 = __fmaf_rn(-2.0f, hi, __fadd_rn(ns1, cn));
                int n = kc + ty * 8 + j;
                if (s0 < bd[i2 * 2])     { bd[i2 * 2]     = s0; bi[i2 * 2]     = n; }
                if (s1 < bd[i2 * 2 + 1]) { bd[i2 * 2 + 1] = s1; bi[i2 * 2 + 1] = n; }
            }
        }
    }

    // cross-thread (over ty) min reduction, reusing smem
    __syncthreads();
    float* rd = (float*)smraw;            // [16][128]
    int*   ri = (int*)(smraw + 8192);     // [16][128]
    #pragma unroll
    for (int i = 0; i < 8; i++) {
        rd[ty * 128 + tx * 8 + i] = bd[i];
        ri[ty * 128 + tx * 8 + i] = bi[i];
    }
    __syncthreads();
    if (tid < 128) {
        float best = rd[tid];
        int   bidx = ri[tid];
        // explicit first-index tiebreak
        for (int t = 1; t < 16; t++) {
            float v  = rd[t * 128 + tid];
            int   vi = ri[t * 128 + tid];
            if (v < best || (v == best && vi < bidx)) { best = v; bidx = vi; }
        }
        g_idx[n0 + tid] = bidx;
        atomicAdd(&g_counts[bidx], 1.0f);   // integer-valued: deterministic
    }
}

// ---------------------------------------------------------------------------
// Kernel 3: gather quantized output + per-block loss partial.
// Loads vectorized; outq = out+1 (4 mod 16) so stores stay scalar.
// ---------------------------------------------------------------------------
__global__ void gather_loss_kernel(const float* __restrict__ in,
                                   const float* __restrict__ cb,
                                   float* __restrict__ outq) {
    const int tid = threadIdx.x;
    const int e   = (blockIdx.x * 256 + tid) * 4;

    int b  = e >> 18;
    int r  = e & 262143;
    int c  = r >> 12;
    int hw = r & 4095;           // multiple of 4
    const int4 gi = *(const int4*)&g_idx[(b << 12) | hw];

    float4 x = *(const float4*)(in + e);
    float q0 = __ldg(&cb[gi.x * DD + c]);
    float q1 = __ldg(&cb[gi.y * DD + c]);
    float q2 = __ldg(&cb[gi.z * DD + c]);
    float q3 = __ldg(&cb[gi.w * DD + c]);

    float d0 = q0 - x.x, d1 = q1 - x.y, d2 = q2 - x.z, d3 = q3 - x.w;
    outq[e + 0] = x.x + d0;
    outq[e + 1] = x.y + d1;
    outq[e + 2] = x.z + d2;
    outq[e + 3] = x.w + d3;
    float part = d0 * d0 + d1 * d1 + d2 * d2 + d3 * d3;

    #pragma unroll
    for (int o2 = 16; o2; o2 >>= 1)
        part += __shfl_xor_sync(0xffffffffu, part, o2);
    __shared__ float ws[8];
    if ((tid & 31) == 0) ws[tid >> 5] = part;
    __syncthreads();
    if (tid == 0) {
        float s = 0.f;
        #pragma unroll
        for (int w = 0; w < 8; w++) s += ws[w];
        g_part[blockIdx.x] = s;
    }
}

// ---------------------------------------------------------------------------
// Kernel 4: finalize loss + perplexity
// ---------------------------------------------------------------------------
__global__ void finalize_kernel(const float* __restrict__ beta,
                                float* __restrict__ loss_out,
                                float* __restrict__ pp_out) {
    const int t = threadIdx.x;   // 1024

    float ls = 0.f;
    #pragma unroll
    for (int i = 0; i < GATHER_BLOCKS / 1024; i++)
        ls += g_part[t * (GATHER_BLOCKS / 1024) + i];

    float em  = g_counts[t] * (1.0f / (float)NPIX);
    float ent = em * logf(em + 1e-10f);

    #pragma unroll
    for (int o = 16; o; o >>= 1) {
        ls  += __shfl_xor_sync(0xffffffffu, ls, o);
        ent += __shfl_xor_sync(0xffffffffu, ent, o);
    }
    __shared__ float wl[32], we[32];
    if ((t & 31) == 0) { wl[t >> 5] = ls; we[t >> 5] = ent; }
    __syncthreads();
    if (t == 0) {
        float tl = 0.f, te = 0.f;
        #pragma unroll
        for (int w = 0; w < 32; w++) { tl += wl[w]; te += we[w]; }
        float mean = tl / (float)NEL;
        *loss_out = (1.0f + *beta) * 10.0f * mean;   // KLD_SCALE = 10
        *pp_out   = expf(-te);
    }
}

// ---------------------------------------------------------------------------
// Launch
// ---------------------------------------------------------------------------
extern "C" void kernel_launch(void* const* d_in, const int* in_sizes, int n_in,
                              void* d_out, int out_size) {
    const float* in   = nullptr;
    const float* cb   = nullptr;
    const float* beta = nullptr;
    for (int i = 0; i < n_in; i++) {
        if      (in_sizes[i] == NEL)     in   = (const float*)d_in[i];
        else if (in_sizes[i] == KK * DD) cb   = (const float*)d_in[i];
        else if (in_sizes[i] == 1)       beta = (const float*)d_in[i];
    }

    float* out      = (float*)d_out;
    float* loss_out = out;
    float* q_out    = out + 1;
    float* pp_out   = out + (out_size - 1);

    const int smem_bytes = 99328;
    cudaFuncSetAttribute(argmin_kernel,
                         cudaFuncAttributeMaxDynamicSharedMemorySize, smem_bytes);

    prep_kernel<<<(KK + 255) / 256, 256>>>(cb);
    argmin_kernel<<<NPIX / TILE_P, 256, smem_bytes>>>(in, cb);
    gather_loss_kernel<<<GATHER_BLOCKS, 256>>>(in, cb, q_out);
    finalize_kernel<<<1, 1024>>>(beta, loss_out, pp_out);
}

// round 11
// speedup vs baseline: 6.2106x; 1.0607x over previous
#include <cuda_runtime.h>
#include <math.h>
#include <stdint.h>

// Problem constants
#define BB    16
#define CC    64
#define HWSZ  4096
#define NPIX  65536
#define KK    1024
#define DD    64
#define NEL   4194304
#define TILE_P 32
#define NTILE  2048            // NPIX / TILE_P
#define CHUNK  256

// Device scratch
__device__ float g_counts[KK];
__device__ float g_cnorm[KK];
__device__ float g_part[NTILE];
__device__ __align__(16) float g_ct[DD * KK];   // transposed codebook: [d][k]

// ---------------------------------------------------------------------------
// Kernel 1: exact cnorm + transposed codebook image + zero histogram
// ---------------------------------------------------------------------------
__global__ void prep_kernel(const float* __restrict__ cb) {
    int k = blockIdx.x * blockDim.x + threadIdx.x;
    if (k >= KK) return;
    float s = 0.f;
    #pragma unroll
    for (int d = 0; d < DD; d++) {
        float v = cb[k * DD + d];
        s = __fadd_rn(s, __fmul_rn(v, v));   // reference-exact cn
        g_ct[d * KK + k] = v;
    }
    g_cnorm[k]  = s;
    g_counts[k] = 0.f;
}

// ---------------------------------------------------------------------------
// Kernel 2: fused exact argmin (fp32 FFMA GEMM) + gather + loss partial.
// 2048 blocks x 256 threads; block = 32 pixels; thread (tx,ty) owns
// pixels tx*4..+3 and codes ty*8..+7 within each 256-code chunk.
// smem: xs f32[64][32] | cs f32[64][260] | cns[256] | nss[32] | sidx[32]
// ---------------------------------------------------------------------------
extern __shared__ char smraw[];

__global__ void __launch_bounds__(256, 2)
argmin_fused_kernel(const float* __restrict__ in, const float* __restrict__ cb,
                    float* __restrict__ outq) {
    float* xs   = (float*)smraw;                   // 8192 B
    float* cs   = (float*)(smraw + 8192);          // 66560 B (64 x 260)
    float* cns  = (float*)(smraw + 74752);         // 1024 B
    float* nss  = (float*)(smraw + 75776);         // 128 B
    int*   sidx = (int*)(smraw + 75904);           // 128 B  (total 76032)

    const int tid = threadIdx.x;
    const int tx  = tid & 7;     // pixel group: pixels tx*4 .. +3
    const int ty  = tid >> 3;    // code group:  codes  ty*8 .. +7 (in chunk)

    const int n0  = blockIdx.x * TILE_P;   // 32 | 4096: never crosses batch
    const int b   = n0 >> 12;
    const int hw0 = n0 & 4095;
    const float* xin = in + (size_t)b * CC * HWSZ + hw0;

    // x tile: xs[d][p] (coalesced 128B rows)
    for (int i = tid; i < DD * TILE_P; i += 256) {
        int d = i >> 5, p = i & 31;
        xs[d * 32 + p] = xin[(size_t)d * HWSZ + p];
    }
    __syncthreads();

    // exact ||x||^2 (reference rounding)
    if (tid < 32) {
        float s = 0.f;
        #pragma unroll
        for (int d = 0; d < DD; d++) {
            float v = xs[d * 32 + tid];
            s = __fadd_rn(s, __fmul_rn(v, v));
        }
        nss[tid] = s;
    }

    float bd[4];
    int   bi[4];
    #pragma unroll
    for (int i = 0; i < 4; i++) { bd[i] = 3.4e38f; bi[i] = 0; }

    for (int kc = 0; kc < KK; kc += CHUNK) {
        __syncthreads();
        // copy transposed chunk: cs[d][0..255] = g_ct[d*1024 + kc ..], uint4
        {
            const uint4* src = (const uint4*)(g_ct + kc);
            uint4* dst = (uint4*)cs;
            #pragma unroll
            for (int r = 0; r < 16; r++) {
                int i = tid + r * 256;            // i < 4096
                int d = i >> 6, g = i & 63;       // 64 uint4 per row
                dst[d * 65 + g] = src[d * 256 + g];
            }
        }
        cns[tid] = g_cnorm[kc + tid];
        __syncthreads();

        float acc[4][8];
        #pragma unroll
        for (int i = 0; i < 4; i++)
            #pragma unroll
            for (int j = 0; j < 8; j++) acc[i][j] = 0.f;

        // dot: strictly d-ascending single-accumulator fp32 FMA chains
        #pragma unroll 2
        for (int d = 0; d < 64; d++) {
            const float4 xa = *(const float4*)(xs + d * 32 + tx * 4);
            const float4 ca = *(const float4*)(cs + d * 260 + ty * 8);
            const float4 cc = *(const float4*)(cs + d * 260 + ty * 8 + 4);
            float xv[4] = {xa.x, xa.y, xa.z, xa.w};
            float cv[8] = {ca.x, ca.y, ca.z, ca.w, cc.x, cc.y, cc.z, cc.w};
            #pragma unroll
            for (int i = 0; i < 4; i++)
                #pragma unroll
                for (int j = 0; j < 8; j++)
                    acc[i][j] = __fmaf_rn(xv[i], cv[j], acc[i][j]);
        }

        // score fl(fl(ns+cn) - fl(2*dot)) == fmaf(-2,dot,fl(ns+cn)) (2*dot exact);
        // ascending n + strict '<' keeps first-index min within thread.
        #pragma unroll
        for (int i = 0; i < 4; i++) {
            float ns = nss[tx * 4 + i];
            #pragma unroll
            for (int j = 0; j < 8; j++) {
                float s = __fmaf_rn(-2.0f, acc[i][j], __fadd_rn(ns, cns[ty * 8 + j]));
                if (s < bd[i]) { bd[i] = s; bi[i] = kc + ty * 8 + j; }
            }
        }
    }

    // cross-thread (over 32 ty groups) min reduction; reuse cs area
    __syncthreads();
    float* rd = (float*)(smraw + 8192);            // [32][32]
    int*   ri = (int*)(smraw + 8192 + 4096);       // [32][32]
    #pragma unroll
    for (int i = 0; i < 4; i++) {
        rd[ty * 32 + tx * 4 + i] = bd[i];
        ri[ty * 32 + tx * 4 + i] = bi[i];
    }
    __syncthreads();
    if (tid < 32) {
        float best = rd[tid];
        int   bidx = ri[tid];
        #pragma unroll
        for (int t = 1; t < 32; t++) {
            float v  = rd[t * 32 + tid];
            int   vi = ri[t * 32 + tid];
            if (v < best || (v == best && vi < bidx)) { best = v; bidx = vi; }
        }
        sidx[tid] = bidx;
        atomicAdd(&g_counts[bidx], 1.0f);   // integer-valued: deterministic
    }
    __syncthreads();

    // fused gather + quantized output + loss partial (xs still valid)
    // thread t: pixel p = t&31, channels c = (t>>5) + 8*ii. Stores coalesced;
    // outq = out+1 is 4-mod-16 aligned so stores are scalar (required).
    {
        const int p = tid & 31;
        const int c0 = tid >> 5;
        const int idx = sidx[p];
        const float* crow = cb + (size_t)idx * DD;
        float* obase = outq + (size_t)b * CC * HWSZ + hw0 + p;
        float part = 0.f;
        #pragma unroll
        for (int ii = 0; ii < 8; ii++) {
            int c = c0 + ii * 8;
            float x = xs[c * 32 + p];
            float q = __ldg(&crow[c]);
            float dv = q - x;
            obase[(size_t)c * HWSZ] = x + dv;
            part = __fmaf_rn(dv, dv, part);
        }
        // deterministic block reduction
        #pragma unroll
        for (int o = 16; o; o >>= 1)
            part += __shfl_xor_sync(0xffffffffu, part, o);
        __shared__ float ws[8];
        if ((tid & 31) == 0) ws[tid >> 5] = part;
        __syncthreads();
        if (tid == 0) {
            float s = 0.f;
            #pragma unroll
            for (int w = 0; w < 8; w++) s += ws[w];
            g_part[blockIdx.x] = s;
        }
    }
}

// ---------------------------------------------------------------------------
// Kernel 3: finalize loss + perplexity
// ---------------------------------------------------------------------------
__global__ void finalize_kernel(const float* __restrict__ beta,
                                float* __restrict__ loss_out,
                                float* __restrict__ pp_out) {
    const int t = threadIdx.x;   // 1024

    float ls = 0.f;
    #pragma unroll
    for (int i = 0; i < NTILE / 1024; i++)
        ls += g_part[t * (NTILE / 1024) + i];

    float em  = g_counts[t] * (1.0f / (float)NPIX);
    float ent = em * logf(em + 1e-10f);

    #pragma unroll
    for (int o = 16; o; o >>= 1) {
        ls  += __shfl_xor_sync(0xffffffffu, ls, o);
        ent += __shfl_xor_sync(0xffffffffu, ent, o);
    }
    __shared__ float wl[32], we[32];
    if ((t & 31) == 0) { wl[t >> 5] = ls; we[t >> 5] = ent; }
    __syncthreads();
    if (t == 0) {
        float tl = 0.f, te = 0.f;
        #pragma unroll
        for (int w = 0; w < 32; w++) { tl += wl[w]; te += we[w]; }
        float mean = tl / (float)NEL;
        *loss_out = (1.0f + *beta) * 10.0f * mean;   // KLD_SCALE = 10
        *pp_out   = expf(-te);
    }
}

// ---------------------------------------------------------------------------
// Launch
// ---------------------------------------------------------------------------
extern "C" void kernel_launch(void* const* d_in, const int* in_sizes, int n_in,
                              void* d_out, int out_size) {
    const float* in   = nullptr;
    const float* cb   = nullptr;
    const float* beta = nullptr;
    for (int i = 0; i < n_in; i++) {
        if      (in_sizes[i] == NEL)     in   = (const float*)d_in[i];
        else if (in_sizes[i] == KK * DD) cb   = (const float*)d_in[i];
        else if (in_sizes[i] == 1)       beta = (const float*)d_in[i];
    }

    float* out      = (float*)d_out;
    float* loss_out = out;
    float* q_out    = out + 1;
    float* pp_out   = out + (out_size - 1);

    const int smem_bytes = 76032;
    cudaFuncSetAttribute(argmin_fused_kernel,
                         cudaFuncAttributeMaxDynamicSharedMemorySize, smem_bytes);

    prep_kernel<<<(KK + 255) / 256, 256>>>(cb);
    argmin_fused_kernel<<<NTILE, 256, smem_bytes>>>(in, cb, q_out);
    finalize_kernel<<<1, 1024>>>(beta, loss_out, pp_out);
}

// round 12
// speedup vs baseline: 6.4732x; 1.0423x over previous
#include <cuda_runtime.h>
#include <math.h>
#include <stdint.h>

// Problem constants
#define BB    16
#define CC    64
#define HWSZ  4096
#define NPIX  65536
#define KK    1024
#define DD    64
#define NEL   4194304
#define TILE_P 128
#define CHUNK  128
#define NTILE  512             // NPIX / TILE_P

// Device scratch
__device__ float g_counts[KK];
__device__ float g_cnorm[KK];
__device__ float g_part[NTILE];

// ---------------------------------------------------------------------------
// Kernel 1: codebook norms (reference rounding) + zero histogram.
// Coalesced: stage 256 codes (64KB, padded rows) in smem, then per-thread
// sequential-d reduction (order mandated by reference bit-exactness).
// ---------------------------------------------------------------------------
extern __shared__ float psm[];

__global__ void prep_kernel(const float* __restrict__ cb) {
    const int tid  = threadIdx.x;
    const int base = blockIdx.x * 256;           // 256 codes per block

    // coalesced load of cb[base .. base+256) x 64 into padded smem rows
    for (int i = tid; i < 256 * DD; i += 256) {
        int k = i >> 6, d = i & 63;
        psm[k * 65 + d] = cb[(size_t)(base + k) * DD + d];
    }
    __syncthreads();

    float s = 0.f;
    #pragma unroll
    for (int d = 0; d < DD; d++) {
        float v = psm[tid * 65 + d];
        s = __fadd_rn(s, __fmul_rn(v, v));       // reference-exact cn
    }
    g_cnorm[base + tid]  = s;
    g_counts[base + tid] = 0.f;
}

// ---------------------------------------------------------------------------
// Kernel 2: fused exact argmin (fp32 FFMA GEMM, R6-proven core) +
//           gather + quantized store + loss partial.
// 512 blocks x 256 threads; block = 128 pixels; thread (tx,ty) owns
// pixels tx*8..+7 and codes ty*8..+7 within each 128-code chunk.
// smem (floats): xs[8192] | cs[8448] | cns[128] | nss[128] | sidx[128]
// ---------------------------------------------------------------------------
extern __shared__ float smem[];

__global__ void __launch_bounds__(256, 2)
argmin_fused_kernel(const float* __restrict__ in, const float* __restrict__ cb,
                    float* __restrict__ outq) {
    float* xs   = smem;                       // 8192 floats
    float* cs   = smem + 8192;                // 8448 floats (64 x 132)
    float* cns  = smem + 16640;               // 128
    float* nss  = smem + 16768;               // 128
    int*   sidx = (int*)(smem + 16896);       // 128 ints  (total 17024 words)

    const int tid = threadIdx.x;
    const int tx  = tid & 15;   // pixel group: pixels tx*8 .. +7
    const int ty  = tid >> 4;   // code group:  codes  ty*8 .. +7 (in chunk)

    const int n0  = blockIdx.x * TILE_P;      // never crosses batch boundary
    const int b   = n0 >> 12;
    const int hw0 = n0 & 4095;
    const float* xin = in + (size_t)b * CC * HWSZ + hw0;

    // load x tile: xs[d][p] (coalesced)
    for (int i = tid; i < 64 * 128; i += 256) {
        int d = i >> 7, p = i & 127;
        xs[d * 128 + p] = xin[(size_t)d * HWSZ + p];
    }
    __syncthreads();

    // exact ||x||^2 (reference rounding)
    if (tid < 128) {
        float s = 0.f;
        #pragma unroll
        for (int d = 0; d < DD; d++) {
            float v = xs[d * 128 + tid];
            s = __fadd_rn(s, __fmul_rn(v, v));
        }
        nss[tid] = s;
    }

    float bd[8];
    int   bi[8];
    #pragma unroll
    for (int i = 0; i < 8; i++) { bd[i] = 3.4e38f; bi[i] = 0; }

    for (int kc = 0; kc < KK; kc += CHUNK) {
        __syncthreads();
        // load codebook chunk transposed: cs[d][k] = cb[kc+k][d]
        for (int i = tid; i < CHUNK * 64; i += 256) {
            int k = i >> 6, d = i & 63;
            cs[d * 132 + k] = cb[(size_t)(kc + k) * DD + d];
        }
        if (tid < CHUNK) cns[tid] = g_cnorm[kc + tid];
        __syncthreads();

        float acc[8][8];
        #pragma unroll
        for (int i = 0; i < 8; i++)
            #pragma unroll
            for (int j = 0; j < 8; j++) acc[i][j] = 0.f;

        // dot: strictly d-ascending single-accumulator fp32 FMA chains
        #pragma unroll 2
        for (int d = 0; d < 64; d++) {
            const float4 xa  = *reinterpret_cast<const float4*>(&xs[d * 128 + tx * 8]);
            const float4 xb2 = *reinterpret_cast<const float4*>(&xs[d * 128 + tx * 8 + 4]);
            const float4 ca  = *reinterpret_cast<const float4*>(&cs[d * 132 + ty * 8]);
            const float4 cb2 = *reinterpret_cast<const float4*>(&cs[d * 132 + ty * 8 + 4]);
            float xv[8] = {xa.x, xa.y, xa.z, xa.w, xb2.x, xb2.y, xb2.z, xb2.w};
            float cv[8] = {ca.x, ca.y, ca.z, ca.w, cb2.x, cb2.y, cb2.z, cb2.w};
            #pragma unroll
            for (int i = 0; i < 8; i++)
                #pragma unroll
                for (int j = 0; j < 8; j++)
                    acc[i][j] = __fmaf_rn(xv[i], cv[j], acc[i][j]);
        }

        // score fl(fl(ns+cn) - fl(2*dot)) == fmaf(-2,dot,fl(ns+cn)) (2*dot exact)
        // ascending k + strict '<' keeps first-index min within this thread.
        #pragma unroll
        for (int i = 0; i < 8; i++) {
            float ns = nss[tx * 8 + i];
            #pragma unroll
            for (int j = 0; j < 8; j++) {
                float s = __fmaf_rn(-2.0f, acc[i][j], __fadd_rn(ns, cns[ty * 8 + j]));
                if (s < bd[i]) { bd[i] = s; bi[i] = kc + ty * 8 + j; }
            }
        }
    }

    // cross-thread (over ty) min reduction in the cs region (xs preserved!)
    __syncthreads();
    float* rd = cs;                            // [16][128] = 2048 floats
    int*   ri = (int*)(cs + 2048);             // [16][128]
    #pragma unroll
    for (int i = 0; i < 8; i++) {
        rd[ty * 128 + tx * 8 + i] = bd[i];
        ri[ty * 128 + tx * 8 + i] = bi[i];
    }
    __syncthreads();
    if (tid < 128) {
        float best = rd[tid];
        int   bidx = ri[tid];
        // explicit first-index tiebreak
        for (int t = 1; t < 16; t++) {
            float v  = rd[t * 128 + tid];
            int   vi = ri[t * 128 + tid];
            if (v < best || (v == best && vi < bidx)) { best = v; bidx = vi; }
        }
        sidx[tid] = bidx;
        atomicAdd(&g_counts[bidx], 1.0f);      // integer-valued: deterministic
    }
    __syncthreads();

    // fused gather + quantized output + loss partial (xs still valid).
    // thread t: pixel p = t&127 (coalesced stores), channels (t>>7)*32 + ii.
    // outq = out+1 is 4-mod-16 aligned -> scalar stores (required).
    {
        const int p  = tid & 127;
        const int c0 = (tid >> 7) * 32;
        const int idx = sidx[p];
        const float* crow = cb + (size_t)idx * DD;
        float* obase = outq + (size_t)b * CC * HWSZ + hw0 + p;
        float part = 0.f;
        #pragma unroll
        for (int ii = 0; ii < 32; ii++) {
            int c = c0 + ii;
            float x  = xs[c * 128 + p];
            float q  = __ldg(&crow[c]);
            float dv = q - x;
            obase[(size_t)c * HWSZ] = x + dv;
            part = __fmaf_rn(dv, dv, part);
        }
        // deterministic block reduction
        #pragma unroll
        for (int o = 16; o; o >>= 1)
            part += __shfl_xor_sync(0xffffffffu, part, o);
        __shared__ float ws[8];
        if ((tid & 31) == 0) ws[tid >> 5] = part;
        __syncthreads();
        if (tid == 0) {
            float s = 0.f;
            #pragma unroll
            for (int w = 0; w < 8; w++) s += ws[w];
            g_part[blockIdx.x] = s;
        }
    }
}

// ---------------------------------------------------------------------------
// Kernel 3: finalize loss + perplexity (1024 threads, deterministic)
// ---------------------------------------------------------------------------
__global__ void finalize_kernel(const float* __restrict__ beta,
                                float* __restrict__ loss_out,
                                float* __restrict__ pp_out) {
    const int t = threadIdx.x;   // 1024

    float ls = (t < NTILE) ? g_part[t] : 0.f;

    float em  = g_counts[t] * (1.0f / (float)NPIX);
    float ent = em * logf(em + 1e-10f);

    #pragma unroll
    for (int o = 16; o; o >>= 1) {
        ls  += __shfl_xor_sync(0xffffffffu, ls, o);
        ent += __shfl_xor_sync(0xffffffffu, ent, o);
    }
    __shared__ float wl[32], we[32];
    if ((t & 31) == 0) { wl[t >> 5] = ls; we[t >> 5] = ent; }
    __syncthreads();
    if (t == 0) {
        float tl = 0.f, te = 0.f;
        #pragma unroll
        for (int w = 0; w < 32; w++) { tl += wl[w]; te += we[w]; }
        float mean = tl / (float)NEL;
        *loss_out = (1.0f + *beta) * 10.0f * mean;   // KLD_SCALE = 10
        *pp_out   = expf(-te);
    }
}

// ---------------------------------------------------------------------------
// Launch
// ---------------------------------------------------------------------------
extern "C" void kernel_launch(void* const* d_in, const int* in_sizes, int n_in,
                              void* d_out, int out_size) {
    const float* in   = nullptr;
    const float* cb   = nullptr;
    const float* beta = nullptr;
    for (int i = 0; i < n_in; i++) {
        if      (in_sizes[i] == NEL)     in   = (const float*)d_in[i];
        else if (in_sizes[i] == KK * DD) cb   = (const float*)d_in[i];
        else if (in_sizes[i] == 1)       beta = (const float*)d_in[i];
    }

    float* out      = (float*)d_out;
    float* loss_out = out;
    float* q_out    = out + 1;
    float* pp_out   = out + (out_size - 1);

    const int prep_smem = 256 * 65 * 4;          // 66560 B
    const int main_smem = 17024 * 4;             // 68096 B
    cudaFuncSetAttribute(prep_kernel,
                         cudaFuncAttributeMaxDynamicSharedMemorySize, prep_smem);
    cudaFuncSetAttribute(argmin_fused_kernel,
                         cudaFuncAttributeMaxDynamicSharedMemorySize, main_smem);

    prep_kernel<<<KK / 256, 256, prep_smem>>>(cb);
    argmin_fused_kernel<<<NTILE, 256, main_smem>>>(in, cb, q_out);
    finalize_kernel<<<1, 1024>>>(beta, loss_out, pp_out);
}

// round 13
// speedup vs baseline: 6.7396x; 1.0412x over previous
#include <cuda_runtime.h>
#include <math.h>
#include <stdint.h>

// Problem constants
#define BB    16
#define CC    64
#define HWSZ  4096
#define NPIX  65536
#define KK    1024
#define DD    64
#define NEL   4194304
#define TILE_P 128
#define CHUNK  128
#define NTILE  512             // NPIX / TILE_P

// Device scratch
__device__ float g_counts[KK];
__device__ float g_cnorm[KK];
__device__ float g_part[NTILE];
__device__ int   g_done;

// ---------------------------------------------------------------------------
// Kernel 1: codebook norms (reference rounding) + zero histogram + reset flag.
// 16 blocks x 256 threads, 64 codes per block (latency-parallel).
// ---------------------------------------------------------------------------
extern __shared__ float psm[];

__global__ void prep_kernel(const float* __restrict__ cb) {
    const int tid  = threadIdx.x;
    const int base = blockIdx.x * 64;            // 64 codes per block

    // coalesced load of cb[base .. base+64) x 64 into padded smem rows
    for (int i = tid; i < 64 * DD; i += 256) {
        int k = i >> 6, d = i & 63;
        psm[k * 65 + d] = cb[(size_t)(base + k) * DD + d];
    }
    __syncthreads();

    if (tid < 64) {
        float s = 0.f;
        #pragma unroll
        for (int d = 0; d < DD; d++) {
            float v = psm[tid * 65 + d];
            s = __fadd_rn(s, __fmul_rn(v, v));   // reference-exact cn
        }
        g_cnorm[base + tid]  = s;
        g_counts[base + tid] = 0.f;
    }
    if (blockIdx.x == 0 && tid == 0) g_done = 0;
}

// ---------------------------------------------------------------------------
// Kernel 2: fused exact argmin (fp32 FFMA GEMM) + gather + quantized store +
//           loss partial + last-block finalize (threadfence reduction).
// 512 blocks x 256 threads; block = 128 pixels; thread (tx,ty) owns
// pixels tx*8..+7 and codes ty*8..+7 within each 128-code chunk.
// smem (floats): xs[8192] | cs[8448] | cns[128] | nss[128] | sidx[128]
// ---------------------------------------------------------------------------
extern __shared__ float smem[];

__global__ void __launch_bounds__(256, 2)
argmin_fused_kernel(const float* __restrict__ in, const float* __restrict__ cb,
                    float* __restrict__ outq,
                    const float* __restrict__ beta,
                    float* __restrict__ loss_out, float* __restrict__ pp_out) {
    float* xs   = smem;                       // 8192 floats
    float* cs   = smem + 8192;                // 8448 floats (64 x 132)
    float* cns  = smem + 16640;               // 128
    float* nss  = smem + 16768;               // 128
    int*   sidx = (int*)(smem + 16896);       // 128 ints  (total 17024 words)

    const int tid = threadIdx.x;
    const int tx  = tid & 15;   // pixel group: pixels tx*8 .. +7
    const int ty  = tid >> 4;   // code group:  codes  ty*8 .. +7 (in chunk)

    const int n0  = blockIdx.x * TILE_P;      // never crosses batch boundary
    const int b   = n0 >> 12;
    const int hw0 = n0 & 4095;
    const float* xin = in + (size_t)b * CC * HWSZ + hw0;

    // load x tile: xs[d][p] (coalesced)
    for (int i = tid; i < 64 * 128; i += 256) {
        int d = i >> 7, p = i & 127;
        xs[d * 128 + p] = xin[(size_t)d * HWSZ + p];
    }
    __syncthreads();

    // exact ||x||^2 (reference rounding)
    if (tid < 128) {
        float s = 0.f;
        #pragma unroll
        for (int d = 0; d < DD; d++) {
            float v = xs[d * 128 + tid];
            s = __fadd_rn(s, __fmul_rn(v, v));
        }
        nss[tid] = s;
    }

    float bd[8];
    int   bi[8];
    #pragma unroll
    for (int i = 0; i < 8; i++) { bd[i] = 3.4e38f; bi[i] = 0; }

    for (int kc = 0; kc < KK; kc += CHUNK) {
        __syncthreads();
        // load codebook chunk transposed: cs[d][k] = cb[kc+k][d]
        for (int i = tid; i < CHUNK * 64; i += 256) {
            int k = i >> 6, d = i & 63;
            cs[d * 132 + k] = cb[(size_t)(kc + k) * DD + d];
        }
        if (tid < CHUNK) cns[tid] = g_cnorm[kc + tid];
        __syncthreads();

        float acc[8][8];
        #pragma unroll
        for (int i = 0; i < 8; i++)
            #pragma unroll
            for (int j = 0; j < 8; j++) acc[i][j] = 0.f;

        // dot: strictly d-ascending single-accumulator fp32 FMA chains
        #pragma unroll 2
        for (int d = 0; d < 64; d++) {
            const float4 xa  = *reinterpret_cast<const float4*>(&xs[d * 128 + tx * 8]);
            const float4 xb2 = *reinterpret_cast<const float4*>(&xs[d * 128 + tx * 8 + 4]);
            const float4 ca  = *reinterpret_cast<const float4*>(&cs[d * 132 + ty * 8]);
            const float4 cb2 = *reinterpret_cast<const float4*>(&cs[d * 132 + ty * 8 + 4]);
            float xv[8] = {xa.x, xa.y, xa.z, xa.w, xb2.x, xb2.y, xb2.z, xb2.w};
            float cv[8] = {ca.x, ca.y, ca.z, ca.w, cb2.x, cb2.y, cb2.z, cb2.w};
            #pragma unroll
            for (int i = 0; i < 8; i++)
                #pragma unroll
                for (int j = 0; j < 8; j++)
                    acc[i][j] = __fmaf_rn(xv[i], cv[j], acc[i][j]);
        }

        // score fl(fl(ns+cn) - fl(2*dot)) == fmaf(-2,dot,fl(ns+cn)) (2*dot exact)
        // ascending k + strict '<' keeps first-index min within this thread.
        #pragma unroll
        for (int i = 0; i < 8; i++) {
            float ns = nss[tx * 8 + i];
            #pragma unroll
            for (int j = 0; j < 8; j++) {
                float s = __fmaf_rn(-2.0f, acc[i][j], __fadd_rn(ns, cns[ty * 8 + j]));
                if (s < bd[i]) { bd[i] = s; bi[i] = kc + ty * 8 + j; }
            }
        }
    }

    // cross-thread (over ty) min reduction in the cs region (xs preserved!)
    __syncthreads();
    float* rd = cs;                            // [16][128]
    int*   ri = (int*)(cs + 2048);             // [16][128]
    #pragma unroll
    for (int i = 0; i < 8; i++) {
        rd[ty * 128 + tx * 8 + i] = bd[i];
        ri[ty * 128 + tx * 8 + i] = bi[i];
    }
    __syncthreads();
    if (tid < 128) {
        float best = rd[tid];
        int   bidx = ri[tid];
        // explicit first-index tiebreak
        for (int t = 1; t < 16; t++) {
            float v  = rd[t * 128 + tid];
            int   vi = ri[t * 128 + tid];
            if (v < best || (v == best && vi < bidx)) { best = v; bidx = vi; }
        }
        sidx[tid] = bidx;
        atomicAdd(&g_counts[bidx], 1.0f);      // integer-valued: deterministic
    }
    __syncthreads();

    // fused gather + quantized output + loss partial (xs still valid).
    // thread t: pixel p = t&127 (coalesced stores), channels (t>>7)*32 + ii.
    // outq = out+1 is 4-mod-16 aligned -> scalar stores (required).
    {
        const int p  = tid & 127;
        const int c0 = (tid >> 7) * 32;
        const int idx = sidx[p];
        const float* crow = cb + (size_t)idx * DD;
        float* obase = outq + (size_t)b * CC * HWSZ + hw0 + p;
        float part = 0.f;
        #pragma unroll
        for (int ii = 0; ii < 32; ii++) {
            int c = c0 + ii;
            float x  = xs[c * 128 + p];
            float q  = __ldg(&crow[c]);
            float dv = q - x;
            obase[(size_t)c * HWSZ] = x + dv;
            part = __fmaf_rn(dv, dv, part);
        }
        // deterministic block reduction
        #pragma unroll
        for (int o = 16; o; o >>= 1)
            part += __shfl_xor_sync(0xffffffffu, part, o);
        __shared__ float ws[8];
        if ((tid & 31) == 0) ws[tid >> 5] = part;
        __syncthreads();
        if (tid == 0) {
            float s = 0.f;
            #pragma unroll
            for (int w = 0; w < 8; w++) s += ws[w];
            g_part[blockIdx.x] = s;
        }
    }

    // ---- last-block finalize (threadfence reduction pattern) ----
    __shared__ int is_last;
    if (tid == 0) {
        __threadfence();
        int v = atomicAdd(&g_done, 1);
        is_last = (v == NTILE - 1) ? 1 : 0;
    }
    __syncthreads();
    if (is_last) {
        __threadfence();   // ensure all blocks' g_part/g_counts visible

        float ls = g_part[tid * 2] + g_part[tid * 2 + 1];

        float ent = 0.f;
        #pragma unroll
        for (int i = 0; i < 4; i++) {
            float em = g_counts[tid * 4 + i] * (1.0f / (float)NPIX);
            ent += em * logf(em + 1e-10f);
        }

        #pragma unroll
        for (int o = 16; o; o >>= 1) {
            ls  += __shfl_xor_sync(0xffffffffu, ls, o);
            ent += __shfl_xor_sync(0xffffffffu, ent, o);
        }
        __shared__ float wl[8], we[8];
        if ((tid & 31) == 0) { wl[tid >> 5] = ls; we[tid >> 5] = ent; }
        __syncthreads();
        if (tid == 0) {
            float tl = 0.f, te = 0.f;
            #pragma unroll
            for (int w = 0; w < 8; w++) { tl += wl[w]; te += we[w]; }
            float mean = tl / (float)NEL;
            *loss_out = (1.0f + *beta) * 10.0f * mean;   // KLD_SCALE = 10
            *pp_out   = expf(-te);
        }
    }
}

// ---------------------------------------------------------------------------
// Launch
// ---------------------------------------------------------------------------
extern "C" void kernel_launch(void* const* d_in, const int* in_sizes, int n_in,
                              void* d_out, int out_size) {
    const float* in   = nullptr;
    const float* cb   = nullptr;
    const float* beta = nullptr;
    for (int i = 0; i < n_in; i++) {
        if      (in_sizes[i] == NEL)     in   = (const float*)d_in[i];
        else if (in_sizes[i] == KK * DD) cb   = (const float*)d_in[i];
        else if (in_sizes[i] == 1)       beta = (const float*)d_in[i];
    }

    float* out      = (float*)d_out;
    float* loss_out = out;
    float* q_out    = out + 1;
    float* pp_out   = out + (out_size - 1);

    const int prep_smem = 64 * 65 * 4;           // 16640 B
    const int main_smem = 17024 * 4;             // 68096 B
    cudaFuncSetAttribute(argmin_fused_kernel,
                         cudaFuncAttributeMaxDynamicSharedMemorySize, main_smem);

    prep_kernel<<<16, 256, prep_smem>>>(cb);
    argmin_fused_kernel<<<NTILE, 256, main_smem>>>(in, cb, q_out,
                                                   beta, loss_out, pp_out);
}